// round 2
// baseline (speedup 1.0000x reference)
#include <cuda_runtime.h>
#include <cstdint>

// Problem constants (fixed by the dataset)
#define BVAL   2048
#define TVAL   2048
#define HVAL   64
#define BTILE  8                 // batches per CTA
#define THREADS (BTILE * HVAL)   // 512: thread = (batch_local, j)

// ---------- packed f32x2 helpers (Blackwell) ----------
__device__ __forceinline__ unsigned long long ffma2(unsigned long long a,
                                                    unsigned long long b,
                                                    unsigned long long c) {
    unsigned long long d;
    asm("fma.rn.f32x2 %0, %1, %2, %3;" : "=l"(d) : "l"(a), "l"(b), "l"(c));
    return d;
}
__device__ __forceinline__ unsigned long long fadd2(unsigned long long a,
                                                    unsigned long long b) {
    unsigned long long d;
    asm("add.rn.f32x2 %0, %1, %2;" : "=l"(d) : "l"(a), "l"(b));
    return d;
}
__device__ __forceinline__ float lo32(unsigned long long v) {
    return __uint_as_float((unsigned)v);
}
__device__ __forceinline__ float hi32(unsigned long long v) {
    return __uint_as_float((unsigned)(v >> 32));
}
__device__ __forceinline__ unsigned long long pack2(float lo, float hi) {
    return (unsigned long long)__float_as_uint(lo) |
           ((unsigned long long)__float_as_uint(hi) << 32);
}

// Accurate-enough fast tanh: tanh(s) = (e^{2s}-1)/(e^{2s}+1) via ex2/rcp approx.
// ex2.approx/rcp.approx are ~1-2 ulp -> tanh rel err ~1e-7 (vs 5e-4 for tanh.approx,
// which would random-walk over 2048 recurrent steps).
__device__ __forceinline__ float fast_tanh(float s) {
    float z = fminf(s * 2.885390082f, 126.0f);   // 2*log2(e)*s, clamp to avoid inf
    float p; asm("ex2.approx.f32 %0, %1;" : "=f"(p) : "f"(z));
    float num = p - 1.0f;
    float den = p + 1.0f;
    float r; asm("rcp.approx.f32 %0, %1;" : "=f"(r) : "f"(den));
    return num * r;   // z very negative -> p=0 -> returns -1 exactly. correct.
}

// Named barrier over one batch's 64 threads (2 warps). ids 1..BTILE.
__device__ __forceinline__ void barrier_batch(int bl) {
    asm volatile("bar.sync %0, 64;" :: "r"(bl + 1) : "memory");
}

__global__ void __launch_bounds__(THREADS, 1)
rnn_kernel(const float* __restrict__ x,     // [B,T,2]
           const float* __restrict__ W_ih,  // [64,2]
           const float* __restrict__ W_hh,  // [64,64]
           const float* __restrict__ b_ih,  // [64]
           const float* __restrict__ b_hh,  // [64]
           const float* __restrict__ W_fc,  // [2,64]
           const float* __restrict__ b_fc,  // [2]
           float* __restrict__ out)         // [B,2]
{
    // double-buffered hidden state, batch-major so each batch's 64 h are contiguous
    __shared__ __align__(16) float hbuf[2][BTILE][HVAL];

    const int tid   = threadIdx.x;
    const int j     = tid & (HVAL - 1);   // output index this thread owns
    const int bl    = tid >> 6;           // local batch 0..7
    const int batch = blockIdx.x * BTILE + bl;

    // W_hh row j, k-packed into 32 x u64 registers (pairs of adjacent k)
    unsigned long long w2[HVAL / 2];
    {
        const unsigned long long* wrow =
            reinterpret_cast<const unsigned long long*>(W_hh + j * HVAL);
        #pragma unroll
        for (int k = 0; k < HVAL / 2; k++) w2[k] = wrow[k];
    }
    const float wih0 = W_ih[2 * j];
    const float wih1 = W_ih[2 * j + 1];
    const float bias = b_ih[j] + b_hh[j];

    // h0 = 0
    hbuf[0][bl][j] = 0.0f;
    barrier_batch(bl);

    const float2* xp = reinterpret_cast<const float2*>(x) + (size_t)batch * TVAL;
    float2 xv = xp[0];

    // one RNN step: read hbuf[RB][bl], write hbuf[WB][bl]
    #define RNN_STEP(RB, WB, XCUR)                                               \
    {                                                                            \
        float base = fmaf((XCUR).x, wih0, fmaf((XCUR).y, wih1, bias));           \
        unsigned long long acc0 = pack2(base, 0.0f);                             \
        unsigned long long acc1 = 0ull;                                          \
        const ulonglong2* hp =                                                   \
            reinterpret_cast<const ulonglong2*>(&hbuf[(RB)][bl][0]);             \
        _Pragma("unroll")                                                        \
        for (int kk = 0; kk < HVAL / 4; kk++) {                                  \
            ulonglong2 hv = hp[kk];            /* LDS.128, warp-broadcast */     \
            acc0 = ffma2(hv.x, w2[2 * kk],     acc0);                            \
            acc1 = ffma2(hv.y, w2[2 * kk + 1], acc1);                            \
        }                                                                        \
        unsigned long long accs = fadd2(acc0, acc1);                             \
        float s  = lo32(accs) + hi32(accs);                                      \
        hbuf[(WB)][bl][j] = fast_tanh(s);                                        \
        barrier_batch(bl);                                                       \
    }

    #pragma unroll 1
    for (int t = 0; t < TVAL; t += 2) {
        float2 xnA = xp[t + 1];                       // always in range (t+1 <= T-1)
        RNN_STEP(0, 1, xv)
        int idx2 = (t + 2 < TVAL) ? (t + 2) : (TVAL - 1);
        float2 xnB = xp[idx2];
        RNN_STEP(1, 0, xnA)
        xv = xnB;
    }
    #undef RNN_STEP

    // Final FC on h_T (lives in hbuf[0] after an even number of steps).
    // O=2: threads j<2 each produce one output scalar for their batch.
    if (j < 2) {
        const float* wfc = W_fc + j * HVAL;
        float acc = b_fc[j];
        #pragma unroll
        for (int k = 0; k < HVAL; k++)
            acc = fmaf(hbuf[0][bl][k], wfc[k], acc);
        out[batch * 2 + j] = acc;
    }
}

extern "C" void kernel_launch(void* const* d_in, const int* in_sizes, int n_in,
                              void* d_out, int out_size) {
    const float* x    = (const float*)d_in[0];
    const float* W_ih = (const float*)d_in[1];
    const float* W_hh = (const float*)d_in[2];
    const float* b_ih = (const float*)d_in[3];
    const float* b_hh = (const float*)d_in[4];
    const float* W_fc = (const float*)d_in[5];
    const float* b_fc = (const float*)d_in[6];
    rnn_kernel<<<BVAL / BTILE, THREADS>>>(x, W_ih, W_hh, b_ih, b_hh,
                                          W_fc, b_fc, (float*)d_out);
}

// round 3
// speedup vs baseline: 1.1039x; 1.1039x over previous
#include <cuda_runtime.h>
#include <cstdint>

// Problem constants (fixed by the dataset)
#define BVAL   2048
#define TVAL   2048
#define HVAL   64
#define GROUPS 7                    // barrier groups per CTA (2 batches each)
#define BTILE  (2 * GROUPS)         // 14 batches per CTA
#define THREADS (GROUPS * HVAL)     // 448 threads
#define GRID   ((BVAL + BTILE - 1) / BTILE)   // 147 CTAs -> single wave

// ---------- packed f32x2 helpers (Blackwell) ----------
__device__ __forceinline__ unsigned long long ffma2(unsigned long long a,
                                                    unsigned long long b,
                                                    unsigned long long c) {
    unsigned long long d;
    asm("fma.rn.f32x2 %0, %1, %2, %3;" : "=l"(d) : "l"(a), "l"(b), "l"(c));
    return d;
}
__device__ __forceinline__ unsigned long long fadd2(unsigned long long a,
                                                    unsigned long long b) {
    unsigned long long d;
    asm("add.rn.f32x2 %0, %1, %2;" : "=l"(d) : "l"(a), "l"(b));
    return d;
}
__device__ __forceinline__ float lo32(unsigned long long v) {
    return __uint_as_float((unsigned)v);
}
__device__ __forceinline__ float hi32(unsigned long long v) {
    return __uint_as_float((unsigned)(v >> 32));
}
__device__ __forceinline__ unsigned long long pack2(float lo, float hi) {
    return (unsigned long long)__float_as_uint(lo) |
           ((unsigned long long)__float_as_uint(hi) << 32);
}

// tanh via ex2/rcp approx: rel err ~1e-7 per step (safe over 2048 recurrent steps).
__device__ __forceinline__ float fast_tanh(float s) {
    float z = fminf(s * 2.885390082f, 126.0f);   // 2*log2(e)*s, clamped
    float p; asm("ex2.approx.f32 %0, %1;" : "=f"(p) : "f"(z));
    float num = p - 1.0f;
    float den = p + 1.0f;
    float r; asm("rcp.approx.f32 %0, %1;" : "=f"(r) : "f"(den));
    return num * r;   // z << 0 -> p = 0 -> exactly -1
}

// Named barrier over one group's 64 threads (2 warps, 2 batches). ids 1..GROUPS.
__device__ __forceinline__ void barrier_group(int g) {
    asm volatile("bar.sync %0, 64;" :: "r"(g + 1) : "memory");
}

__global__ void __launch_bounds__(THREADS, 1)
rnn_kernel(const float* __restrict__ x,     // [B,T,2]
           const float* __restrict__ W_ih,  // [64,2]
           const float* __restrict__ W_hh,  // [64,64]
           const float* __restrict__ b_ih,  // [64]
           const float* __restrict__ b_hh,  // [64]
           const float* __restrict__ W_fc,  // [2,64]
           const float* __restrict__ b_fc,  // [2]
           float* __restrict__ out)         // [B,2]
{
    // double-buffered hidden state, batch-major (contiguous 64 floats per batch)
    __shared__ __align__(16) float hbuf[2][BTILE][HVAL];

    const int tid = threadIdx.x;
    const int j   = tid & (HVAL - 1);   // output index this thread owns
    const int g   = tid >> 6;           // group 0..6
    const int bl0 = 2 * g;              // local batch pair
    const int b0  = blockIdx.x * BTILE + bl0;
    if (b0 >= BVAL) return;             // whole group exits together (pairs aligned)

    // W_hh row j, k-packed into 32 x u64 registers
    unsigned long long w2[HVAL / 2];
    {
        const unsigned long long* wrow =
            reinterpret_cast<const unsigned long long*>(W_hh + j * HVAL);
        #pragma unroll
        for (int k = 0; k < HVAL / 2; k++) w2[k] = wrow[k];
    }
    const float wih0 = W_ih[2 * j];
    const float wih1 = W_ih[2 * j + 1];
    const float bias = b_ih[j] + b_hh[j];

    // h0 = 0 for both batches of the pair
    hbuf[0][bl0 + 0][j] = 0.0f;
    hbuf[0][bl0 + 1][j] = 0.0f;
    barrier_group(g);

    // x as float4 = two timesteps per load, per batch
    const float4* xq0 = reinterpret_cast<const float4*>(x + (size_t)b0 * TVAL * 2);
    const float4* xq1 = reinterpret_cast<const float4*>(x + (size_t)(b0 + 1) * TVAL * 2);
    float4 c0 = xq0[0];
    float4 c1 = xq1[0];

    // one RNN step for both batches: read hbuf[RB], write hbuf[WB]
    #define RNN_STEP(RB, WB, XA0, XB0, XA1, XB1)                                 \
    {                                                                            \
        float base0 = fmaf((XA0), wih0, fmaf((XB0), wih1, bias));                \
        float base1 = fmaf((XA1), wih0, fmaf((XB1), wih1, bias));                \
        unsigned long long a00 = pack2(base0, 0.0f), a01 = 0ull;                 \
        unsigned long long a10 = pack2(base1, 0.0f), a11 = 0ull;                 \
        const ulonglong2* hp0 =                                                  \
            reinterpret_cast<const ulonglong2*>(&hbuf[(RB)][bl0 + 0][0]);        \
        const ulonglong2* hp1 =                                                  \
            reinterpret_cast<const ulonglong2*>(&hbuf[(RB)][bl0 + 1][0]);        \
        _Pragma("unroll")                                                        \
        for (int kk = 0; kk < HVAL / 4; kk++) {                                  \
            ulonglong2 hv0 = hp0[kk];          /* LDS.128, broadcast */          \
            ulonglong2 hv1 = hp1[kk];                                            \
            a00 = ffma2(hv0.x, w2[2 * kk],     a00);                             \
            a01 = ffma2(hv0.y, w2[2 * kk + 1], a01);                             \
            a10 = ffma2(hv1.x, w2[2 * kk],     a10);                             \
            a11 = ffma2(hv1.y, w2[2 * kk + 1], a11);                             \
        }                                                                        \
        unsigned long long s0p = fadd2(a00, a01);                                \
        unsigned long long s1p = fadd2(a10, a11);                                \
        float s0 = lo32(s0p) + hi32(s0p);                                        \
        float s1 = lo32(s1p) + hi32(s1p);                                        \
        hbuf[(WB)][bl0 + 0][j] = fast_tanh(s0);                                  \
        hbuf[(WB)][bl0 + 1][j] = fast_tanh(s1);                                  \
        barrier_group(g);                                                        \
    }

    #pragma unroll 1
    for (int t = 0; t < TVAL; t += 2) {
        // prefetch next pair of timesteps (clamped on the last iteration)
        int tn = (t + 2 < TVAL) ? (t / 2 + 1) : (TVAL / 2 - 1);
        float4 n0 = xq0[tn];
        float4 n1 = xq1[tn];
        RNN_STEP(0, 1, c0.x, c0.y, c1.x, c1.y)
        RNN_STEP(1, 0, c0.z, c0.w, c1.z, c1.w)
        c0 = n0;
        c1 = n1;
    }
    #undef RNN_STEP

    // Final FC on h_T (in hbuf[0] after an even number of steps). O=2, 2 batches:
    // threads j<4 cover (batch_in_pair, output) combinations.
    if (j < 4) {
        const int which = j >> 1;         // 0 -> b0, 1 -> b1
        const int oj    = j & 1;          // output index 0/1
        const float* hv  = &hbuf[0][bl0 + which][0];
        const float* wfc = W_fc + oj * HVAL;
        float acc = b_fc[oj];
        #pragma unroll
        for (int k = 0; k < HVAL; k++)
            acc = fmaf(hv[k], wfc[k], acc);
        out[(b0 + which) * 2 + oj] = acc;
    }
}

extern "C" void kernel_launch(void* const* d_in, const int* in_sizes, int n_in,
                              void* d_out, int out_size) {
    const float* x    = (const float*)d_in[0];
    const float* W_ih = (const float*)d_in[1];
    const float* W_hh = (const float*)d_in[2];
    const float* b_ih = (const float*)d_in[3];
    const float* b_hh = (const float*)d_in[4];
    const float* W_fc = (const float*)d_in[5];
    const float* b_fc = (const float*)d_in[6];
    rnn_kernel<<<GRID, THREADS>>>(x, W_ih, W_hh, b_ih, b_hh,
                                  W_fc, b_fc, (float*)d_out);
}